// round 2
// baseline (speedup 1.0000x reference)
#include <cuda_runtime.h>
#include <cuda_fp16.h>
#include <cstdint>

// Problem dims
#define MT 8192   // 4 * 2048 rows of x
#define KD 4096   // in_features
#define ND 4096   // out_features

// Scratch (device globals: allocation-free rule)
__device__ __half g_Wh[(size_t)ND * KD];   // 32 MB fp16 dequantized weights, row-major [o][i]
__device__ __half g_Xh[(size_t)MT * KD];   // 64 MB fp16 activations, row-major [m][k]

__constant__ float c_nf4[16] = {
    -1.0f, -0.6961928009986877f, -0.5250730514526367f, -0.39491748809814453f,
    -0.28444138169288635f, -0.18477343022823334f, -0.09105003625154495f, 0.0f,
    0.07958029955625534f, 0.16093020141124725f, 0.24611230194568634f,
    0.33791524171829224f, 0.44070982933044434f, 0.5626170039176941f,
    0.7229568362236023f, 1.0f};

// ---------------------------------------------------------------------------
// Kernel 1: NF4 dequant.  packed is int32-per-byte, (O, K/2) row-major.
// Each thread: 4 packed ints (int4 load) -> 8 fp16 weights (int4 store).
// ---------------------------------------------------------------------------
__global__ void k_dequant(const int4* __restrict__ packed,
                          const float* __restrict__ absmax) {
    int t = blockIdx.x * blockDim.x + threadIdx.x;     // 0 .. N*K/8 - 1
    int4 p = packed[t];
    int row = t / (KD / 8);                            // 512 groups per row
    float am = absmax[row];
    int v[4] = {p.x, p.y, p.z, p.w};
    __half h[8];
#pragma unroll
    for (int j = 0; j < 4; j++) {
        int b = v[j] & 255;
        h[2 * j]     = __float2half(c_nf4[(b >> 4) & 15] * am);
        h[2 * j + 1] = __float2half(c_nf4[b & 15] * am);
    }
    *reinterpret_cast<int4*>(&g_Wh[(size_t)t * 8]) = *reinterpret_cast<int4*>(h);
}

// ---------------------------------------------------------------------------
// Kernel 2: x f32 -> f16 convert.  Each thread: 8 floats -> 8 halfs.
// ---------------------------------------------------------------------------
__global__ void k_convert(const float4* __restrict__ x) {
    int t = blockIdx.x * blockDim.x + threadIdx.x;     // 0 .. M*K/8 - 1
    float4 a = x[2 * t];
    float4 b = x[2 * t + 1];
    __half h[8];
    h[0] = __float2half(a.x); h[1] = __float2half(a.y);
    h[2] = __float2half(a.z); h[3] = __float2half(a.w);
    h[4] = __float2half(b.x); h[5] = __float2half(b.y);
    h[6] = __float2half(b.z); h[7] = __float2half(b.w);
    *reinterpret_cast<int4*>(&g_Xh[(size_t)t * 8]) = *reinterpret_cast<int4*>(h);
}

// ---------------------------------------------------------------------------
// Kernel 3: GEMM  C[m][n] = sum_k Xh[m][k] * Wh[n][k] + bias[n]
// 128x128 block tile, BK=32, cp.async double buffer, ldmatrix + mma m16n8k16.
// 8 warps: 2 (M) x 4 (N), each warp 64x32.
// ---------------------------------------------------------------------------
#define BM 128
#define BN 128
#define BK 32
#define PADK 40   // BK + 8 halves padding -> conflict-free ldmatrix

__device__ __forceinline__ uint32_t smem_u32(const void* p) {
    return (uint32_t)__cvta_generic_to_shared(p);
}

__global__ __launch_bounds__(256) void k_gemm(const float* __restrict__ bias,
                                              float* __restrict__ out) {
    __shared__ __half As[2][BM][PADK];
    __shared__ __half Bs[2][BN][PADK];

    const int tid  = threadIdx.x;
    const int lane = tid & 31;
    const int warp = tid >> 5;
    const int wm   = warp >> 2;   // 0..1
    const int wn   = warp & 3;    // 0..3

    const int bm = blockIdx.y * BM;
    const int bn = blockIdx.x * BN;

    const __half* gA = g_Xh + (size_t)bm * KD;
    const __half* gB = g_Wh + (size_t)bn * KD;

    float acc[4][4][4];
#pragma unroll
    for (int mi = 0; mi < 4; mi++)
#pragma unroll
        for (int ni = 0; ni < 4; ni++)
#pragma unroll
            for (int j = 0; j < 4; j++) acc[mi][ni][j] = 0.0f;

    // tile loader: 512 16B chunks per operand, 2 per thread
    auto load_tile = [&](int buf, int k0) {
#pragma unroll
        for (int i = 0; i < 2; i++) {
            int c   = tid + i * 256;
            int row = c >> 2;
            int col = (c & 3) * 8;
            uint32_t sa = smem_u32(&As[buf][row][col]);
            const __half* ga = gA + (size_t)row * KD + k0 + col;
            asm volatile("cp.async.cg.shared.global [%0], [%1], 16;\n" :: "r"(sa), "l"(ga));
            uint32_t sb = smem_u32(&Bs[buf][row][col]);
            const __half* gb = gB + (size_t)row * KD + k0 + col;
            asm volatile("cp.async.cg.shared.global [%0], [%1], 16;\n" :: "r"(sb), "l"(gb));
        }
        asm volatile("cp.async.commit_group;\n" ::: "memory");
    };

    load_tile(0, 0);
    asm volatile("cp.async.wait_group 0;\n" ::: "memory");
    __syncthreads();

    const int a_row    = lane & 15;
    const int a_colsel = (lane >> 4) * 8;
    const int b_row    = lane & 7;
    const int b_colsel = ((lane >> 3) & 1) * 8;

    int buf = 0;
    const int KT = KD / BK;  // 128
    for (int kt = 0; kt < KT; kt++) {
        if (kt + 1 < KT) load_tile(buf ^ 1, (kt + 1) * BK);

#pragma unroll
        for (int ks = 0; ks < 2; ks++) {
            uint32_t af[4][4];
#pragma unroll
            for (int mi = 0; mi < 4; mi++) {
                uint32_t addr = smem_u32(&As[buf][wm * 64 + mi * 16 + a_row][ks * 16 + a_colsel]);
                asm volatile("ldmatrix.sync.aligned.m8n8.x4.shared.b16 {%0,%1,%2,%3}, [%4];\n"
                             : "=r"(af[mi][0]), "=r"(af[mi][1]), "=r"(af[mi][2]), "=r"(af[mi][3])
                             : "r"(addr));
            }
            uint32_t bf[4][2];
#pragma unroll
            for (int ni = 0; ni < 4; ni++) {
                uint32_t addr = smem_u32(&Bs[buf][wn * 32 + ni * 8 + b_row][ks * 16 + b_colsel]);
                asm volatile("ldmatrix.sync.aligned.m8n8.x2.shared.b16 {%0,%1}, [%2];\n"
                             : "=r"(bf[ni][0]), "=r"(bf[ni][1])
                             : "r"(addr));
            }
#pragma unroll
            for (int mi = 0; mi < 4; mi++)
#pragma unroll
                for (int ni = 0; ni < 4; ni++) {
                    asm volatile(
                        "mma.sync.aligned.m16n8k16.row.col.f32.f16.f16.f32 "
                        "{%0,%1,%2,%3}, {%4,%5,%6,%7}, {%8,%9}, {%0,%1,%2,%3};\n"
                        : "+f"(acc[mi][ni][0]), "+f"(acc[mi][ni][1]),
                          "+f"(acc[mi][ni][2]), "+f"(acc[mi][ni][3])
                        : "r"(af[mi][0]), "r"(af[mi][1]), "r"(af[mi][2]), "r"(af[mi][3]),
                          "r"(bf[ni][0]), "r"(bf[ni][1]));
                }
        }

        asm volatile("cp.async.wait_group 0;\n" ::: "memory");
        __syncthreads();
        buf ^= 1;
    }

    // Epilogue: add bias, write fp32
    const int gr = lane >> 2;
    const int gc = (lane & 3) * 2;
#pragma unroll
    for (int mi = 0; mi < 4; mi++) {
#pragma unroll
        for (int ni = 0; ni < 4; ni++) {
            int m0 = bm + wm * 64 + mi * 16 + gr;
            int n0 = bn + wn * 32 + ni * 8 + gc;
            float b0 = bias[n0];
            float b1 = bias[n0 + 1];
            float2 v0 = make_float2(acc[mi][ni][0] + b0, acc[mi][ni][1] + b1);
            float2 v1 = make_float2(acc[mi][ni][2] + b0, acc[mi][ni][3] + b1);
            *reinterpret_cast<float2*>(&out[(size_t)m0 * ND + n0]) = v0;
            *reinterpret_cast<float2*>(&out[(size_t)(m0 + 8) * ND + n0]) = v1;
        }
    }
}

// ---------------------------------------------------------------------------
extern "C" void kernel_launch(void* const* d_in, const int* in_sizes, int n_in,
                              void* d_out, int out_size) {
    const float* x      = (const float*)d_in[0];
    const int*   packed = (const int*)d_in[1];
    const float* absmax = (const float*)d_in[2];
    const float* bias   = (const float*)d_in[3];
    float*       out    = (float*)d_out;

    // 1) dequant W: N*K/8 threads
    k_dequant<<<(ND * (KD / 8)) / 256, 256>>>((const int4*)packed, absmax);
    // 2) convert x: M*K/8 threads
    k_convert<<<(MT * (KD / 8)) / 256, 256>>>((const float4*)x);
    // 3) GEMM
    dim3 grid(ND / BN, MT / BM);  // (32, 64)
    k_gemm<<<grid, 256>>>(bias, out);
}